// round 4
// baseline (speedup 1.0000x reference)
#include <cuda_runtime.h>
#include <cuda_bf16.h>
#include <math.h>
#include <stdint.h>

#define NROWS 8192
#define DIM 512
#define LOGIT_SCALE 2.659f

// ---------------- device scratch ----------------
__device__ __nv_bfloat16 g_Abf[NROWS * DIM];   // normalized image features (bf16)
__device__ __nv_bfloat16 g_Bbf[NROWS * DIM];   // normalized text features (bf16)
__device__ float g_rowZ[NROWS], g_rowS[NROWS], g_colZ[NROWS], g_colS[NROWS];
__device__ int   g_lab[NROWS];
__device__ int   g_hist[1024];
__device__ int   g_is64;

// ---------------- fast exp on the FMA pipe (|x| <= ~3, rel err ~2e-6) ----------------
__device__ __forceinline__ float fexp(float s) {
    float t = s * 1.4426950408889634f;
    float z = t + 12582912.0f;
    int   n = __float_as_int(z) - 0x4B400000;
    float nf = z - 12582912.0f;
    float f = t - nf;
    float p = 1.3333558146e-3f;
    p = fmaf(p, f, 9.6181291076e-3f);
    p = fmaf(p, f, 5.5504108665e-2f);
    p = fmaf(p, f, 2.4022650696e-1f);
    p = fmaf(p, f, 6.9314718056e-1f);
    p = fmaf(p, f, 1.0f);
    return __int_as_float(__float_as_int(p) + (n << 23));
}

// ---------------- async copy helpers ----------------
#define CP_ASYNC16(dst, src) \
    asm volatile("cp.async.cg.shared.global [%0], [%1], 16;" :: "r"(dst), "l"(src))
#define CP_COMMIT() asm volatile("cp.async.commit_group;" ::: "memory")
#define CP_WAIT(n)  asm volatile("cp.async.wait_group %0;" :: "n"(n) : "memory")

__device__ __forceinline__ uint32_t smem_u32(const void* p) {
    uint32_t a;
    asm("{ .reg .u64 t; cvta.to.shared.u64 t, %1; cvt.u32.u64 %0, t; }" : "=r"(a) : "l"(p));
    return a;
}

__device__ __forceinline__ void ldmatrix_x4(uint32_t& r0, uint32_t& r1, uint32_t& r2,
                                            uint32_t& r3, uint32_t addr) {
    asm volatile("ldmatrix.sync.aligned.m8n8.x4.shared.b16 {%0,%1,%2,%3}, [%4];"
                 : "=r"(r0), "=r"(r1), "=r"(r2), "=r"(r3) : "r"(addr));
}

__device__ __forceinline__ void mma_16816(float* d, const uint32_t* a, const uint32_t* b) {
    asm volatile(
        "mma.sync.aligned.m16n8k16.row.col.f32.bf16.bf16.f32 "
        "{%0,%1,%2,%3}, {%4,%5,%6,%7}, {%8,%9}, {%0,%1,%2,%3};"
        : "+f"(d[0]), "+f"(d[1]), "+f"(d[2]), "+f"(d[3])
        : "r"(a[0]), "r"(a[1]), "r"(a[2]), "r"(a[3]), "r"(b[0]), "r"(b[1]));
}

// ---------------- label dtype detect (int64 vs int32) ----------------
__global__ void k_detect(const int* __restrict__ w) {
    int ok = 1;
    for (int p = threadIdx.x; p < 4096; p += blockDim.x) {
        int lo = w[2 * p], hi = w[2 * p + 1];
        if (hi != (lo >> 31)) ok = 0;
    }
    ok = __syncthreads_and(ok);
    if (threadIdx.x == 0) g_is64 = ok;
}

// ---------------- init ----------------
__global__ void k_init(const void* __restrict__ labels) {
    int i = blockIdx.x * 256 + threadIdx.x;
    if (i < 1024) g_hist[i] = 0;
    if (i >= NROWS) return;
    int lab = g_is64 ? (int)((const long long*)labels)[i] : ((const int*)labels)[i];
    g_lab[i] = lab;
    g_rowZ[i] = 0.f; g_rowS[i] = 0.f;
    g_colZ[i] = 0.f; g_colS[i] = 0.f;
}

__global__ void k_hist() {
    int i = blockIdx.x * 256 + threadIdx.x;
    int l = g_lab[i];
    if (l >= 0) atomicAdd(&g_hist[l & 1023], 1);
}

// ---------------- normalize + cast to bf16 ----------------
__global__ void k_norm(const float* __restrict__ img, const float* __restrict__ txt) {
    int b = blockIdx.x;
    const float* src; __nv_bfloat16* dst; int row;
    if (b < NROWS) { src = img; dst = g_Abf; row = b; }
    else           { src = txt; dst = g_Bbf; row = b - NROWS; }
    float4 v = ((const float4*)(src + (size_t)row * DIM))[threadIdx.x];
    float ss = v.x * v.x + v.y * v.y + v.z * v.z + v.w * v.w;
#pragma unroll
    for (int m = 16; m; m >>= 1) ss += __shfl_xor_sync(0xffffffffu, ss, m);
    __shared__ float ws[4];
    if ((threadIdx.x & 31) == 0) ws[threadIdx.x >> 5] = ss;
    __syncthreads();
    float inv = rsqrtf(fmaxf(ws[0] + ws[1] + ws[2] + ws[3], 1e-24f));
    __nv_bfloat162 p0 = __float22bfloat162_rn(make_float2(v.x * inv, v.y * inv));
    __nv_bfloat162 p1 = __float22bfloat162_rn(make_float2(v.z * inv, v.w * inv));
    uint2 o;
    o.x = *(uint32_t*)&p0;
    o.y = *(uint32_t*)&p1;
    *(uint2*)(dst + (size_t)row * DIM + threadIdx.x * 4) = o;
}

// ---------------- fused bf16 mma.sync GEMM + softmax-stat epilogue ----------------
// CTA tile 128(m) x 256(n), BK=32, 3-stage cp.async pipeline, 8 warps in a
// 2(m) x 4(n) grid -> warp tile 64x64 (4 m16 frags x 8 n8 frags).
// Smem stage: A 128x32 bf16 (8KB) + B 256x32 bf16 (16KB) in 8x8-tile-blocked
// layout: tile t = (row>>3)*4 + (k>>3), elem (row&7)*16; ldmatrix.x4-friendly.
#define STAGE_BYTES 24576

__global__ __launch_bounds__(256) void k_gemm() {
    extern __shared__ char smem[];
    const uint32_t sbase = smem_u32(smem);
    const int tid = threadIdx.x;
    const int lane = tid & 31, wid = tid >> 5;
    const int wm = wid & 1, wn = wid >> 1;            // 2 x 4 warp grid
    const int i0 = blockIdx.y * 128, j0 = blockIdx.x * 256;

    const int ldr = tid >> 2;        // 0..63
    const int ldc = tid & 3;         // 8-col chunk

    const int g = lane >> 3;         // lane group 0..3
    const int lr = lane & 7;
    uint32_t aOff[4][2], bOff[4][2];
#pragma unroll
    for (int mt = 0; mt < 4; mt++)
#pragma unroll
        for (int ks = 0; ks < 2; ks++)
            aOff[mt][ks] = (uint32_t)(((wm * 8 + mt * 2 + (g & 1)) * 4 +
                                       (ks * 2 + (g >> 1))) * 128 + lr * 16);
#pragma unroll
    for (int np = 0; np < 4; np++)
#pragma unroll
        for (int ks = 0; ks < 2; ks++)
            bOff[np][ks] = (uint32_t)(8192 + ((wn * 8 + np * 2 + (g >> 1)) * 4 +
                                              (ks * 2 + (g & 1))) * 128 + lr * 16);

    float acc[4][8][4];
#pragma unroll
    for (int mt = 0; mt < 4; mt++)
#pragma unroll
        for (int nt = 0; nt < 8; nt++)
#pragma unroll
            for (int e = 0; e < 4; e++) acc[mt][nt][e] = 0.f;

    auto load_stage = [&](int s, int kk) {
        uint32_t sA = sbase + s * STAGE_BYTES;
        uint32_t sB = sA + 8192;
        {
            uint32_t doff = (uint32_t)(((ldr >> 3) * 4 + ldc) * 128 + (ldr & 7) * 16);
            CP_ASYNC16(sA + doff, g_Abf + (size_t)(i0 + ldr) * DIM + kk + ldc * 8);
            int r = ldr + 64;
            uint32_t doff2 = (uint32_t)(((r >> 3) * 4 + ldc) * 128 + (r & 7) * 16);
            CP_ASYNC16(sA + doff2, g_Abf + (size_t)(i0 + r) * DIM + kk + ldc * 8);
        }
#pragma unroll
        for (int h = 0; h < 4; h++) {
            int r = ldr + h * 64;
            uint32_t doff = (uint32_t)(((r >> 3) * 4 + ldc) * 128 + (r & 7) * 16);
            CP_ASYNC16(sB + doff, g_Bbf + (size_t)(j0 + r) * DIM + kk + ldc * 8);
        }
    };

    load_stage(0, 0);
    CP_COMMIT();
    load_stage(1, 32);
    CP_COMMIT();

    int slot = 0;          // slot of stage `it`
    int nslot = 2;         // slot for stage `it+2`
    for (int it = 0; it < 16; it++) {
        if (it <= 13) CP_WAIT(1); else CP_WAIT(0);
        __syncthreads();
        if (it + 2 <= 15) {
            load_stage(nslot, (it + 2) * 32);
            CP_COMMIT();
        }
        uint32_t stg = sbase + slot * STAGE_BYTES;
#pragma unroll
        for (int ks = 0; ks < 2; ks++) {
            uint32_t A[4][4];
#pragma unroll
            for (int mt = 0; mt < 4; mt++)
                ldmatrix_x4(A[mt][0], A[mt][1], A[mt][2], A[mt][3], stg + aOff[mt][ks]);
            uint32_t B[8][2];
#pragma unroll
            for (int np = 0; np < 4; np++) {
                uint32_t b0, b1, b2, b3;
                ldmatrix_x4(b0, b1, b2, b3, stg + bOff[np][ks]);
                B[np * 2][0] = b0;     B[np * 2][1] = b1;
                B[np * 2 + 1][0] = b2; B[np * 2 + 1][1] = b3;
            }
#pragma unroll
            for (int mt = 0; mt < 4; mt++)
#pragma unroll
                for (int nt = 0; nt < 8; nt++)
                    mma_16816(acc[mt][nt], A[mt], B[nt]);
        }
        slot = (slot == 2) ? 0 : slot + 1;
        nslot = (nslot == 2) ? 0 : nslot + 1;
    }

    // ---- epilogue: logits -> exp + target-weighted stats (registers only) ----
    const int r_base = i0 + wm * 64 + (lane >> 2);       // + mt*16 + hb*8
    const int c_base = j0 + wn * 64 + 2 * (lane & 3);    // + nt*8 + d

    int labR[8];
#pragma unroll
    for (int q = 0; q < 8; q++) labR[q] = g_lab[r_base + (q >> 1) * 16 + (q & 1) * 8];
    int labC[16];
#pragma unroll
    for (int nt = 0; nt < 8; nt++) {
        labC[nt * 2]     = g_lab[c_base + nt * 8];
        labC[nt * 2 + 1] = g_lab[c_base + nt * 8 + 1];
    }

    float rZ[8], rS[8], cZ[16], cS[16];
#pragma unroll
    for (int q = 0; q < 8; q++) { rZ[q] = 0.f; rS[q] = 0.f; }
#pragma unroll
    for (int q = 0; q < 16; q++) { cZ[q] = 0.f; cS[q] = 0.f; }

#pragma unroll
    for (int mt = 0; mt < 4; mt++)
#pragma unroll
        for (int nt = 0; nt < 8; nt++)
#pragma unroll
            for (int e = 0; e < 4; e++) {
                int hb = e >> 1, d = e & 1;
                float sv = LOGIT_SCALE * acc[mt][nt][e];
                float ex = fexp(sv);
                int gi = r_base + mt * 16 + hb * 8;
                int gj = c_base + nt * 8 + d;
                int li = labR[mt * 2 + hb];
                bool tg = (gi == gj) || (li >= 0 && li == labC[nt * 2 + d]);
                float ms = tg ? sv : 0.f;
                rZ[mt * 2 + hb] += ex; rS[mt * 2 + hb] += ms;
                cZ[nt * 2 + d] += ex;  cS[nt * 2 + d] += ms;
            }

    // rows: reduce across the 4 lanes of each quad
#pragma unroll
    for (int m = 1; m <= 2; m <<= 1)
#pragma unroll
        for (int q = 0; q < 8; q++) {
            rZ[q] += __shfl_xor_sync(0xffffffffu, rZ[q], m);
            rS[q] += __shfl_xor_sync(0xffffffffu, rS[q], m);
        }
    if ((lane & 3) == 0) {
#pragma unroll
        for (int q = 0; q < 8; q++) {
            int gi = r_base + (q >> 1) * 16 + (q & 1) * 8;
            atomicAdd(&g_rowZ[gi], rZ[q]);
            atomicAdd(&g_rowS[gi], rS[q]);
        }
    }

    // cols: reduce across lane>>2
#pragma unroll
    for (int m = 4; m <= 16; m <<= 1)
#pragma unroll
        for (int q = 0; q < 16; q++) {
            cZ[q] += __shfl_xor_sync(0xffffffffu, cZ[q], m);
            cS[q] += __shfl_xor_sync(0xffffffffu, cS[q], m);
        }
    if (lane < 4) {
#pragma unroll
        for (int q = 0; q < 16; q++) {
            int gj = j0 + wn * 64 + (q >> 1) * 8 + 2 * lane + (q & 1);
            atomicAdd(&g_colZ[gj], cZ[q]);
            atomicAdd(&g_colS[gj], cS[q]);
        }
    }
}

// ---------------- final reduction (includes cnt from histogram) ----------------
__global__ void k_final(float* __restrict__ out) {
    int tid = threadIdx.x;
    float sum = 0.f;
    for (int i = tid; i < NROWS; i += 1024) {
        int l = g_lab[i];
        float inv = (l < 0) ? 1.f : 1.f / (float)g_hist[l & 1023];
        sum += logf(g_rowZ[i]) + logf(g_colZ[i]) - (g_rowS[i] + g_colS[i]) * inv;
    }
#pragma unroll
    for (int m = 16; m; m >>= 1) sum += __shfl_xor_sync(0xffffffffu, sum, m);
    __shared__ float ws[32];
    if ((tid & 31) == 0) ws[tid >> 5] = sum;
    __syncthreads();
    if (tid < 32) {
        float v = ws[tid];
#pragma unroll
        for (int m = 16; m; m >>= 1) v += __shfl_xor_sync(0xffffffffu, v, m);
        if (tid == 0) out[0] = v / (2.0f * NROWS);
    }
}

// ---------------- launch ----------------
extern "C" void kernel_launch(void* const* d_in, const int* in_sizes, int n_in,
                              void* d_out, int out_size) {
    const float* txt = (const float*)d_in[0];
    const float* img = (const float*)d_in[1];
    const void*  lab = d_in[2];

    cudaFuncSetAttribute(k_gemm, cudaFuncAttributeMaxDynamicSharedMemorySize,
                         3 * STAGE_BYTES);

    k_detect<<<1, 256>>>((const int*)lab);
    k_init<<<32, 256>>>(lab);
    k_hist<<<32, 256>>>();
    k_norm<<<2 * NROWS, 128>>>(img, txt);
    dim3 grid(32, 64);   // x: 8192/256 j-tiles, y: 8192/128 i-tiles
    k_gemm<<<grid, 256, 3 * STAGE_BYTES>>>();
    k_final<<<1, 1024>>>((float*)d_out);
}

// round 5
// speedup vs baseline: 1.0359x; 1.0359x over previous
#include <cuda_runtime.h>
#include <cuda_fp16.h>
#include <math.h>
#include <stdint.h>

#define NROWS 8192
#define DIM 512
#define LOGIT_SCALE 2.659f

// ---------------- device scratch ----------------
__device__ __half g_Ah[NROWS * DIM];   // normalized image features (fp16)
__device__ __half g_Bh[NROWS * DIM];   // normalized text features (fp16)
__device__ float g_rowZ[NROWS], g_rowS[NROWS], g_colZ[NROWS], g_colS[NROWS];
__device__ int   g_lab[NROWS];
__device__ int   g_hist[1024];
__device__ int   g_is64;

// ---------------- fast exp on the FMA pipe (|x| <= ~3, rel err ~2e-6) ----------------
__device__ __forceinline__ float fexp(float s) {
    float t = s * 1.4426950408889634f;
    float z = t + 12582912.0f;
    int   n = __float_as_int(z) - 0x4B400000;
    float nf = z - 12582912.0f;
    float f = t - nf;
    float p = 1.3333558146e-3f;
    p = fmaf(p, f, 9.6181291076e-3f);
    p = fmaf(p, f, 5.5504108665e-2f);
    p = fmaf(p, f, 2.4022650696e-1f);
    p = fmaf(p, f, 6.9314718056e-1f);
    p = fmaf(p, f, 1.0f);
    return __int_as_float(__float_as_int(p) + (n << 23));
}

// ---------------- async copy helpers ----------------
#define CP_ASYNC16(dst, src) \
    asm volatile("cp.async.cg.shared.global [%0], [%1], 16;" :: "r"(dst), "l"(src))
#define CP_COMMIT() asm volatile("cp.async.commit_group;" ::: "memory")
#define CP_WAIT(n)  asm volatile("cp.async.wait_group %0;" :: "n"(n) : "memory")

__device__ __forceinline__ uint32_t smem_u32(const void* p) {
    uint32_t a;
    asm("{ .reg .u64 t; cvta.to.shared.u64 t, %1; cvt.u32.u64 %0, t; }" : "=r"(a) : "l"(p));
    return a;
}

__device__ __forceinline__ void ldmatrix_x4(uint32_t& r0, uint32_t& r1, uint32_t& r2,
                                            uint32_t& r3, uint32_t addr) {
    asm volatile("ldmatrix.sync.aligned.m8n8.x4.shared.b16 {%0,%1,%2,%3}, [%4];"
                 : "=r"(r0), "=r"(r1), "=r"(r2), "=r"(r3) : "r"(addr));
}

// fp16 in, fp16 accumulate: D(2 regs of half2) = A*B + D
__device__ __forceinline__ void mma_16816_f16(uint32_t* d, const uint32_t* a,
                                              const uint32_t* b) {
    asm volatile(
        "mma.sync.aligned.m16n8k16.row.col.f16.f16.f16.f16 "
        "{%0,%1}, {%2,%3,%4,%5}, {%6,%7}, {%0,%1};"
        : "+r"(d[0]), "+r"(d[1])
        : "r"(a[0]), "r"(a[1]), "r"(a[2]), "r"(a[3]), "r"(b[0]), "r"(b[1]));
}

// ---------------- label dtype detect (int64 vs int32) ----------------
__global__ void k_detect(const int* __restrict__ w) {
    int ok = 1;
    for (int p = threadIdx.x; p < 4096; p += blockDim.x) {
        int lo = w[2 * p], hi = w[2 * p + 1];
        if (hi != (lo >> 31)) ok = 0;
    }
    ok = __syncthreads_and(ok);
    if (threadIdx.x == 0) g_is64 = ok;
}

// ---------------- init ----------------
__global__ void k_init(const void* __restrict__ labels) {
    int i = blockIdx.x * 256 + threadIdx.x;
    if (i < 1024) g_hist[i] = 0;
    if (i >= NROWS) return;
    int lab = g_is64 ? (int)((const long long*)labels)[i] : ((const int*)labels)[i];
    g_lab[i] = lab;
    g_rowZ[i] = 0.f; g_rowS[i] = 0.f;
    g_colZ[i] = 0.f; g_colS[i] = 0.f;
}

__global__ void k_hist() {
    int i = blockIdx.x * 256 + threadIdx.x;
    int l = g_lab[i];
    if (l >= 0) atomicAdd(&g_hist[l & 1023], 1);
}

// ---------------- normalize + cast to fp16 ----------------
__global__ void k_norm(const float* __restrict__ img, const float* __restrict__ txt) {
    int b = blockIdx.x;
    const float* src; __half* dst; int row;
    if (b < NROWS) { src = img; dst = g_Ah; row = b; }
    else           { src = txt; dst = g_Bh; row = b - NROWS; }
    float4 v = ((const float4*)(src + (size_t)row * DIM))[threadIdx.x];
    float ss = v.x * v.x + v.y * v.y + v.z * v.z + v.w * v.w;
#pragma unroll
    for (int m = 16; m; m >>= 1) ss += __shfl_xor_sync(0xffffffffu, ss, m);
    __shared__ float ws[4];
    if ((threadIdx.x & 31) == 0) ws[threadIdx.x >> 5] = ss;
    __syncthreads();
    float inv = rsqrtf(fmaxf(ws[0] + ws[1] + ws[2] + ws[3], 1e-24f));
    __half2 p0 = __float22half2_rn(make_float2(v.x * inv, v.y * inv));
    __half2 p1 = __float22half2_rn(make_float2(v.z * inv, v.w * inv));
    uint2 o;
    o.x = *(uint32_t*)&p0;
    o.y = *(uint32_t*)&p1;
    *(uint2*)(dst + (size_t)row * DIM + threadIdx.x * 4) = o;
}

// ---------------- fused fp16 mma.sync GEMM + softmax-stat epilogue ----------------
// CTA tile 128(m) x 256(n), BK=32, 3-stage cp.async pipeline, 8 warps in a
// 2(m) x 4(n) grid -> warp tile 64x64 (4 m16 frags x 8 n8 frags, fp16 acc).
// Smem stage: A 128x32 fp16 (8KB) + B 256x32 fp16 (16KB) in 8x8-tile-blocked
// layout: tile t = (row>>3)*4 + (k>>3), elem (row&7)*16; ldmatrix.x4-friendly.
#define STAGE_BYTES 24576

__global__ __launch_bounds__(256) void k_gemm() {
    extern __shared__ char smem[];
    const uint32_t sbase = smem_u32(smem);
    const int tid = threadIdx.x;
    const int lane = tid & 31, wid = tid >> 5;
    const int wm = wid & 1, wn = wid >> 1;            // 2 x 4 warp grid
    const int i0 = blockIdx.y * 128, j0 = blockIdx.x * 256;

    const int ldr = tid >> 2;        // 0..63
    const int ldc = tid & 3;         // 8-col chunk

    const int g = lane >> 3;         // lane group 0..3
    const int lr = lane & 7;
    uint32_t aOff[4][2], bOff[4][2];
#pragma unroll
    for (int mt = 0; mt < 4; mt++)
#pragma unroll
        for (int ks = 0; ks < 2; ks++)
            aOff[mt][ks] = (uint32_t)(((wm * 8 + mt * 2 + (g & 1)) * 4 +
                                       (ks * 2 + (g >> 1))) * 128 + lr * 16);
#pragma unroll
    for (int np = 0; np < 4; np++)
#pragma unroll
        for (int ks = 0; ks < 2; ks++)
            bOff[np][ks] = (uint32_t)(8192 + ((wn * 8 + np * 2 + (g >> 1)) * 4 +
                                              (ks * 2 + (g & 1))) * 128 + lr * 16);

    uint32_t acc[4][8][2];   // fp16 accumulators (half2 pairs)
#pragma unroll
    for (int mt = 0; mt < 4; mt++)
#pragma unroll
        for (int nt = 0; nt < 8; nt++) { acc[mt][nt][0] = 0u; acc[mt][nt][1] = 0u; }

    auto load_stage = [&](int s, int kk) {
        uint32_t sA = sbase + s * STAGE_BYTES;
        uint32_t sB = sA + 8192;
#pragma unroll
        for (int h = 0; h < 2; h++) {
            int r = ldr + h * 64;
            uint32_t doff = (uint32_t)(((r >> 3) * 4 + ldc) * 128 + (r & 7) * 16);
            CP_ASYNC16(sA + doff, g_Ah + (size_t)(i0 + r) * DIM + kk + ldc * 8);
        }
#pragma unroll
        for (int h = 0; h < 4; h++) {
            int r = ldr + h * 64;
            uint32_t doff = (uint32_t)(((r >> 3) * 4 + ldc) * 128 + (r & 7) * 16);
            CP_ASYNC16(sB + doff, g_Bh + (size_t)(j0 + r) * DIM + kk + ldc * 8);
        }
    };

    load_stage(0, 0);
    CP_COMMIT();
    load_stage(1, 32);
    CP_COMMIT();

    int slot = 0, nslot = 2;
    for (int it = 0; it < 16; it++) {
        if (it <= 13) CP_WAIT(1); else CP_WAIT(0);
        __syncthreads();
        if (it + 2 <= 15) {
            load_stage(nslot, (it + 2) * 32);
            CP_COMMIT();
        }
        uint32_t stg = sbase + slot * STAGE_BYTES;
#pragma unroll
        for (int ks = 0; ks < 2; ks++) {
            uint32_t A[4][4];
#pragma unroll
            for (int mt = 0; mt < 4; mt++)
                ldmatrix_x4(A[mt][0], A[mt][1], A[mt][2], A[mt][3], stg + aOff[mt][ks]);
            uint32_t B[8][2];
#pragma unroll
            for (int np = 0; np < 4; np++) {
                uint32_t b0, b1, b2, b3;
                ldmatrix_x4(b0, b1, b2, b3, stg + bOff[np][ks]);
                B[np * 2][0] = b0;     B[np * 2][1] = b1;
                B[np * 2 + 1][0] = b2; B[np * 2 + 1][1] = b3;
            }
#pragma unroll
            for (int mt = 0; mt < 4; mt++)
#pragma unroll
                for (int nt = 0; nt < 8; nt++)
                    mma_16816_f16(acc[mt][nt], A[mt], B[nt]);
        }
        slot = (slot == 2) ? 0 : slot + 1;
        nslot = (nslot == 2) ? 0 : nslot + 1;
    }

    // ---- epilogue: logits -> exp + target-weighted stats (registers only) ----
    // acc[mt][nt][hb] is half2 {col c, col c+1} for row (lane>>2)+mt*16+hb*8,
    // cols c = 2*(lane&3)+nt*8.
    const int r_base = i0 + wm * 64 + (lane >> 2);
    const int c_base = j0 + wn * 64 + 2 * (lane & 3);

    int labR[8];
#pragma unroll
    for (int q = 0; q < 8; q++) labR[q] = g_lab[r_base + (q >> 1) * 16 + (q & 1) * 8];
    int labC[16];
#pragma unroll
    for (int nt = 0; nt < 8; nt++) {
        labC[nt * 2]     = g_lab[c_base + nt * 8];
        labC[nt * 2 + 1] = g_lab[c_base + nt * 8 + 1];
    }

    float rZ[8], rS[8], cZ[16], cS[16];
#pragma unroll
    for (int q = 0; q < 8; q++) { rZ[q] = 0.f; rS[q] = 0.f; }
#pragma unroll
    for (int q = 0; q < 16; q++) { cZ[q] = 0.f; cS[q] = 0.f; }

#pragma unroll
    for (int mt = 0; mt < 4; mt++)
#pragma unroll
        for (int nt = 0; nt < 8; nt++)
#pragma unroll
            for (int hb = 0; hb < 2; hb++) {
                float2 pv = __half22float2(*(__half2*)&acc[mt][nt][hb]);
                int gi = r_base + mt * 16 + hb * 8;
                int li = labR[mt * 2 + hb];
#pragma unroll
                for (int d = 0; d < 2; d++) {
                    float sv = LOGIT_SCALE * (d ? pv.y : pv.x);
                    float ex = fexp(sv);
                    int gj = c_base + nt * 8 + d;
                    bool tg = (gi == gj) || (li >= 0 && li == labC[nt * 2 + d]);
                    float ms = tg ? sv : 0.f;
                    rZ[mt * 2 + hb] += ex; rS[mt * 2 + hb] += ms;
                    cZ[nt * 2 + d] += ex;  cS[nt * 2 + d] += ms;
                }
            }

    // rows: reduce across the 4 lanes of each quad
#pragma unroll
    for (int m = 1; m <= 2; m <<= 1)
#pragma unroll
        for (int q = 0; q < 8; q++) {
            rZ[q] += __shfl_xor_sync(0xffffffffu, rZ[q], m);
            rS[q] += __shfl_xor_sync(0xffffffffu, rS[q], m);
        }
    if ((lane & 3) == 0) {
#pragma unroll
        for (int q = 0; q < 8; q++) {
            int gi = r_base + (q >> 1) * 16 + (q & 1) * 8;
            atomicAdd(&g_rowZ[gi], rZ[q]);
            atomicAdd(&g_rowS[gi], rS[q]);
        }
    }

    // cols: reduce across lane>>2
#pragma unroll
    for (int m = 4; m <= 16; m <<= 1)
#pragma unroll
        for (int q = 0; q < 16; q++) {
            cZ[q] += __shfl_xor_sync(0xffffffffu, cZ[q], m);
            cS[q] += __shfl_xor_sync(0xffffffffu, cS[q], m);
        }
    if (lane < 4) {
#pragma unroll
        for (int q = 0; q < 16; q++) {
            int gj = j0 + wn * 64 + (q >> 1) * 8 + 2 * lane + (q & 1);
            atomicAdd(&g_colZ[gj], cZ[q]);
            atomicAdd(&g_colS[gj], cS[q]);
        }
    }
}

// ---------------- final reduction (includes cnt from histogram) ----------------
__global__ void k_final(float* __restrict__ out) {
    int tid = threadIdx.x;
    float sum = 0.f;
    for (int i = tid; i < NROWS; i += 1024) {
        int l = g_lab[i];
        float inv = (l < 0) ? 1.f : 1.f / (float)g_hist[l & 1023];
        sum += logf(g_rowZ[i]) + logf(g_colZ[i]) - (g_rowS[i] + g_colS[i]) * inv;
    }
#pragma unroll
    for (int m = 16; m; m >>= 1) sum += __shfl_xor_sync(0xffffffffu, sum, m);
    __shared__ float ws[32];
    if ((tid & 31) == 0) ws[tid >> 5] = sum;
    __syncthreads();
    if (tid < 32) {
        float v = ws[tid];
#pragma unroll
        for (int m = 16; m; m >>= 1) v += __shfl_xor_sync(0xffffffffu, v, m);
        if (tid == 0) out[0] = v / (2.0f * NROWS);
    }
}

// ---------------- launch ----------------
extern "C" void kernel_launch(void* const* d_in, const int* in_sizes, int n_in,
                              void* d_out, int out_size) {
    const float* txt = (const float*)d_in[0];
    const float* img = (const float*)d_in[1];
    const void*  lab = d_in[2];

    cudaFuncSetAttribute(k_gemm, cudaFuncAttributeMaxDynamicSharedMemorySize,
                         3 * STAGE_BYTES);

    k_detect<<<1, 256>>>((const int*)lab);
    k_init<<<32, 256>>>(lab);
    k_hist<<<32, 256>>>();
    k_norm<<<2 * NROWS, 128>>>(img, txt);
    dim3 grid(32, 64);   // x: 8192/256 j-tiles, y: 8192/128 i-tiles
    k_gemm<<<grid, 256, 3 * STAGE_BYTES>>>();
    k_final<<<1, 1024>>>((float*)d_out);
}

// round 6
// speedup vs baseline: 1.0536x; 1.0171x over previous
#include <cuda_runtime.h>
#include <cuda_fp16.h>
#include <math.h>
#include <stdint.h>

#define NROWS 8192
#define DIM 512
#define LOGIT_SCALE 2.659f
#define QSCALE 16.0f          // feature pre-scale before e4m3 quantization
#define INV_QS2 (1.0f / (QSCALE * QSCALE))

// ---------------- device scratch ----------------
__device__ uint8_t g_A8[NROWS * DIM];   // normalized image features (e4m3, x16)
__device__ uint8_t g_B8[NROWS * DIM];   // normalized text features (e4m3, x16)
__device__ float g_rowZ[NROWS], g_rowS[NROWS], g_colZ[NROWS], g_colS[NROWS];
__device__ int   g_lab[NROWS];
__device__ int   g_hist[1024];
__device__ int   g_is64;

// ---------------- fast exp on the FMA pipe (|x| <= ~3, rel err ~2e-6) ----------------
__device__ __forceinline__ float fexp(float s) {
    float t = s * 1.4426950408889634f;
    float z = t + 12582912.0f;
    int   n = __float_as_int(z) - 0x4B400000;
    float nf = z - 12582912.0f;
    float f = t - nf;
    float p = 1.3333558146e-3f;
    p = fmaf(p, f, 9.6181291076e-3f);
    p = fmaf(p, f, 5.5504108665e-2f);
    p = fmaf(p, f, 2.4022650696e-1f);
    p = fmaf(p, f, 6.9314718056e-1f);
    p = fmaf(p, f, 1.0f);
    return __int_as_float(__float_as_int(p) + (n << 23));
}

// ---------------- async copy helpers ----------------
#define CP_ASYNC16(dst, src) \
    asm volatile("cp.async.cg.shared.global [%0], [%1], 16;" :: "r"(dst), "l"(src))
#define CP_COMMIT() asm volatile("cp.async.commit_group;" ::: "memory")
#define CP_WAIT(n)  asm volatile("cp.async.wait_group %0;" :: "n"(n) : "memory")

__device__ __forceinline__ uint32_t smem_u32(const void* p) {
    uint32_t a;
    asm("{ .reg .u64 t; cvta.to.shared.u64 t, %1; cvt.u32.u64 %0, t; }" : "=r"(a) : "l"(p));
    return a;
}

__device__ __forceinline__ void ldmatrix_x4(uint32_t& r0, uint32_t& r1, uint32_t& r2,
                                            uint32_t& r3, uint32_t addr) {
    asm volatile("ldmatrix.sync.aligned.m8n8.x4.shared.b16 {%0,%1,%2,%3}, [%4];"
                 : "=r"(r0), "=r"(r1), "=r"(r2), "=r"(r3) : "r"(addr));
}

// e4m3 x e4m3 -> f32 accumulate, m16n8k32
__device__ __forceinline__ void mma_fp8(float* d, const uint32_t* a, const uint32_t* b) {
    asm volatile(
        "mma.sync.aligned.m16n8k32.row.col.f32.e4m3.e4m3.f32 "
        "{%0,%1,%2,%3}, {%4,%5,%6,%7}, {%8,%9}, {%0,%1,%2,%3};"
        : "+f"(d[0]), "+f"(d[1]), "+f"(d[2]), "+f"(d[3])
        : "r"(a[0]), "r"(a[1]), "r"(a[2]), "r"(a[3]), "r"(b[0]), "r"(b[1]));
}

// pack two floats into two e4m3 bytes (hi, lo)
__device__ __forceinline__ uint16_t pack_e4m3x2(float hi, float lo) {
    uint16_t r;
    asm("cvt.rn.satfinite.e4m3x2.f32 %0, %1, %2;" : "=h"(r) : "f"(hi), "f"(lo));
    return r;
}

// ---------------- label dtype detect (int64 vs int32) ----------------
__global__ void k_detect(const int* __restrict__ w) {
    int ok = 1;
    for (int p = threadIdx.x; p < 4096; p += blockDim.x) {
        int lo = w[2 * p], hi = w[2 * p + 1];
        if (hi != (lo >> 31)) ok = 0;
    }
    ok = __syncthreads_and(ok);
    if (threadIdx.x == 0) g_is64 = ok;
}

// ---------------- init ----------------
__global__ void k_init(const void* __restrict__ labels) {
    int i = blockIdx.x * 256 + threadIdx.x;
    if (i < 1024) g_hist[i] = 0;
    if (i >= NROWS) return;
    int lab = g_is64 ? (int)((const long long*)labels)[i] : ((const int*)labels)[i];
    g_lab[i] = lab;
    g_rowZ[i] = 0.f; g_rowS[i] = 0.f;
    g_colZ[i] = 0.f; g_colS[i] = 0.f;
}

__global__ void k_hist() {
    int i = blockIdx.x * 256 + threadIdx.x;
    int l = g_lab[i];
    if (l >= 0) atomicAdd(&g_hist[l & 1023], 1);
}

// ---------------- normalize + scale + cast to e4m3 ----------------
__global__ void k_norm(const float* __restrict__ img, const float* __restrict__ txt) {
    int b = blockIdx.x;
    const float* src; uint8_t* dst; int row;
    if (b < NROWS) { src = img; dst = g_A8; row = b; }
    else           { src = txt; dst = g_B8; row = b - NROWS; }
    float4 v = ((const float4*)(src + (size_t)row * DIM))[threadIdx.x];
    float ss = v.x * v.x + v.y * v.y + v.z * v.z + v.w * v.w;
#pragma unroll
    for (int m = 16; m; m >>= 1) ss += __shfl_xor_sync(0xffffffffu, ss, m);
    __shared__ float ws[4];
    if ((threadIdx.x & 31) == 0) ws[threadIdx.x >> 5] = ss;
    __syncthreads();
    float inv = QSCALE * rsqrtf(fmaxf(ws[0] + ws[1] + ws[2] + ws[3], 1e-24f));
    uint16_t lo = pack_e4m3x2(v.y * inv, v.x * inv);
    uint16_t hi = pack_e4m3x2(v.w * inv, v.z * inv);
    uint32_t o = (uint32_t)lo | ((uint32_t)hi << 16);
    *(uint32_t*)(dst + (size_t)row * DIM + threadIdx.x * 4) = o;
}

// ---------------- fused fp8 mma.sync GEMM + softmax-stat epilogue ----------------
// CTA tile 128(m) x 256(n), BK=64 bytes, 3-stage cp.async pipeline, 8 warps in
// 2(m) x 4(n) grid -> warp tile 64x64. Per k-iter: 2 k32 steps, 32 mma each.
// Smem stage: A 128x64B (8KB) + B 256x64B (16KB), 8-row x 16B blocked tiles:
//   tile t = (row>>3)*4 + (kbyte>>4), elem (row&7)*16  (ldmatrix.x4-friendly).
#define STAGE_BYTES 24576

__global__ __launch_bounds__(256) void k_gemm() {
    extern __shared__ char smem[];
    const uint32_t sbase = smem_u32(smem);
    const int tid = threadIdx.x;
    const int lane = tid & 31, wid = tid >> 5;
    const int wm = wid & 1, wn = wid >> 1;            // 2 x 4 warp grid
    const int i0 = blockIdx.y * 128, j0 = blockIdx.x * 256;

    const int ldr = tid >> 2;        // 0..63
    const int ldc = tid & 3;         // 16-byte chunk within the 64B stage row

    const int g = lane >> 3;         // lane group 0..3
    const int lr = lane & 7;
    uint32_t aOff[4][2], bOff[4][2];
#pragma unroll
    for (int mt = 0; mt < 4; mt++)
#pragma unroll
        for (int ks = 0; ks < 2; ks++)
            aOff[mt][ks] = (uint32_t)(((wm * 8 + mt * 2 + (g & 1)) * 4 +
                                       (ks * 2 + (g >> 1))) * 128 + lr * 16);
#pragma unroll
    for (int np = 0; np < 4; np++)
#pragma unroll
        for (int ks = 0; ks < 2; ks++)
            bOff[np][ks] = (uint32_t)(8192 + ((wn * 8 + np * 2 + (g >> 1)) * 4 +
                                              (ks * 2 + (g & 1))) * 128 + lr * 16);

    float acc[4][8][4];
#pragma unroll
    for (int mt = 0; mt < 4; mt++)
#pragma unroll
        for (int nt = 0; nt < 8; nt++)
#pragma unroll
            for (int e = 0; e < 4; e++) acc[mt][nt][e] = 0.f;

    auto load_stage = [&](int s, int kk) {
        uint32_t sA = sbase + s * STAGE_BYTES;
        uint32_t sB = sA + 8192;
#pragma unroll
        for (int h = 0; h < 2; h++) {
            int r = ldr + h * 64;
            uint32_t doff = (uint32_t)(((r >> 3) * 4 + ldc) * 128 + (r & 7) * 16);
            CP_ASYNC16(sA + doff, g_A8 + (size_t)(i0 + r) * DIM + kk + ldc * 16);
        }
#pragma unroll
        for (int h = 0; h < 4; h++) {
            int r = ldr + h * 64;
            uint32_t doff = (uint32_t)(((r >> 3) * 4 + ldc) * 128 + (r & 7) * 16);
            CP_ASYNC16(sB + doff, g_B8 + (size_t)(j0 + r) * DIM + kk + ldc * 16);
        }
    };

    load_stage(0, 0);
    CP_COMMIT();
    load_stage(1, 64);
    CP_COMMIT();

    int slot = 0, nslot = 2;
    for (int it = 0; it < 8; it++) {
        if (it <= 5) CP_WAIT(1); else CP_WAIT(0);
        __syncthreads();
        if (it + 2 <= 7) {
            load_stage(nslot, (it + 2) * 64);
            CP_COMMIT();
        }
        uint32_t stg = sbase + slot * STAGE_BYTES;
#pragma unroll
        for (int ks = 0; ks < 2; ks++) {
            uint32_t A[4][4];
#pragma unroll
            for (int mt = 0; mt < 4; mt++)
                ldmatrix_x4(A[mt][0], A[mt][1], A[mt][2], A[mt][3], stg + aOff[mt][ks]);
            uint32_t B[8][2];
#pragma unroll
            for (int np = 0; np < 4; np++) {
                uint32_t b0, b1, b2, b3;
                ldmatrix_x4(b0, b1, b2, b3, stg + bOff[np][ks]);
                B[np * 2][0] = b0;     B[np * 2][1] = b1;
                B[np * 2 + 1][0] = b2; B[np * 2 + 1][1] = b3;
            }
#pragma unroll
            for (int mt = 0; mt < 4; mt++)
#pragma unroll
                for (int nt = 0; nt < 8; nt++)
                    mma_fp8(acc[mt][nt], A[mt], B[nt]);
        }
        slot = (slot == 2) ? 0 : slot + 1;
        nslot = (nslot == 2) ? 0 : nslot + 1;
    }

    // ---- epilogue: logits -> exp + target-weighted stats (registers only) ----
    const int r_base = i0 + wm * 64 + (lane >> 2);       // + mt*16 + hb*8
    const int c_base = j0 + wn * 64 + 2 * (lane & 3);    // + nt*8 + d
    const float lsc = LOGIT_SCALE * INV_QS2;

    int labR[8];
#pragma unroll
    for (int q = 0; q < 8; q++) labR[q] = g_lab[r_base + (q >> 1) * 16 + (q & 1) * 8];
    int labC[16];
#pragma unroll
    for (int nt = 0; nt < 8; nt++) {
        labC[nt * 2]     = g_lab[c_base + nt * 8];
        labC[nt * 2 + 1] = g_lab[c_base + nt * 8 + 1];
    }

    float rZ[8], rS[8], cZ[16], cS[16];
#pragma unroll
    for (int q = 0; q < 8; q++) { rZ[q] = 0.f; rS[q] = 0.f; }
#pragma unroll
    for (int q = 0; q < 16; q++) { cZ[q] = 0.f; cS[q] = 0.f; }

#pragma unroll
    for (int mt = 0; mt < 4; mt++)
#pragma unroll
        for (int nt = 0; nt < 8; nt++)
#pragma unroll
            for (int e = 0; e < 4; e++) {
                int hb = e >> 1, d = e & 1;
                float sv = lsc * acc[mt][nt][e];
                float ex = fexp(sv);
                int gi = r_base + mt * 16 + hb * 8;
                int gj = c_base + nt * 8 + d;
                int li = labR[mt * 2 + hb];
                bool tg = (gi == gj) || (li >= 0 && li == labC[nt * 2 + d]);
                float ms = tg ? sv : 0.f;
                rZ[mt * 2 + hb] += ex; rS[mt * 2 + hb] += ms;
                cZ[nt * 2 + d] += ex;  cS[nt * 2 + d] += ms;
            }

    // rows: reduce across the 4 lanes of each quad
#pragma unroll
    for (int m = 1; m <= 2; m <<= 1)
#pragma unroll
        for (int q = 0; q < 8; q++) {
            rZ[q] += __shfl_xor_sync(0xffffffffu, rZ[q], m);
            rS[q] += __shfl_xor_sync(0xffffffffu, rS[q], m);
        }
    if ((lane & 3) == 0) {
#pragma unroll
        for (int q = 0; q < 8; q++) {
            int gi = r_base + (q >> 1) * 16 + (q & 1) * 8;
            atomicAdd(&g_rowZ[gi], rZ[q]);
            atomicAdd(&g_rowS[gi], rS[q]);
        }
    }

    // cols: reduce across lane>>2
#pragma unroll
    for (int m = 4; m <= 16; m <<= 1)
#pragma unroll
        for (int q = 0; q < 16; q++) {
            cZ[q] += __shfl_xor_sync(0xffffffffu, cZ[q], m);
            cS[q] += __shfl_xor_sync(0xffffffffu, cS[q], m);
        }
    if (lane < 4) {
#pragma unroll
        for (int q = 0; q < 16; q++) {
            int gj = j0 + wn * 64 + (q >> 1) * 8 + 2 * lane + (q & 1);
            atomicAdd(&g_colZ[gj], cZ[q]);
            atomicAdd(&g_colS[gj], cS[q]);
        }
    }
}

// ---------------- final reduction (includes cnt from histogram) ----------------
__global__ void k_final(float* __restrict__ out) {
    int tid = threadIdx.x;
    float sum = 0.f;
    for (int i = tid; i < NROWS; i += 1024) {
        int l = g_lab[i];
        float inv = (l < 0) ? 1.f : 1.f / (float)g_hist[l & 1023];
        sum += logf(g_rowZ[i]) + logf(g_colZ[i]) - (g_rowS[i] + g_colS[i]) * inv;
    }
#pragma unroll
    for (int m = 16; m; m >>= 1) sum += __shfl_xor_sync(0xffffffffu, sum, m);
    __shared__ float ws[32];
    if ((tid & 31) == 0) ws[tid >> 5] = sum;
    __syncthreads();
    if (tid < 32) {
        float v = ws[tid];
#pragma unroll
        for (int m = 16; m; m >>= 1) v += __shfl_xor_sync(0xffffffffu, v, m);
        if (tid == 0) out[0] = v / (2.0f * NROWS);
    }
}

// ---------------- launch ----------------
extern "C" void kernel_launch(void* const* d_in, const int* in_sizes, int n_in,
                              void* d_out, int out_size) {
    const float* txt = (const float*)d_in[0];
    const float* img = (const float*)d_in[1];
    const void*  lab = d_in[2];

    cudaFuncSetAttribute(k_gemm, cudaFuncAttributeMaxDynamicSharedMemorySize,
                         3 * STAGE_BYTES);

    k_detect<<<1, 256>>>((const int*)lab);
    k_init<<<32, 256>>>(lab);
    k_hist<<<32, 256>>>();
    k_norm<<<2 * NROWS, 128>>>(img, txt);
    dim3 grid(32, 64);   // x: 8192/256 j-tiles, y: 8192/128 i-tiles
    k_gemm<<<grid, 256, 3 * STAGE_BYTES>>>();
    k_final<<<1, 1024>>>((float*)d_out);
}

// round 7
// speedup vs baseline: 1.3869x; 1.3164x over previous
#include <cuda_runtime.h>
#include <cuda_fp16.h>
#include <math.h>
#include <stdint.h>

#define NROWS 8192
#define DIM 512
#define LOGIT_SCALE 2.659f
#define QSCALE 16.0f          // feature pre-scale before e4m3 quantization
#define INV_QS2 (1.0f / (QSCALE * QSCALE))

// ---------------- device scratch ----------------
__device__ uint8_t g_A8[NROWS * DIM];   // normalized image features (e4m3, x16)
__device__ uint8_t g_B8[NROWS * DIM];   // normalized text features (e4m3, x16)
__device__ float g_rowZ[NROWS], g_rowS[NROWS], g_colZ[NROWS], g_colS[NROWS];
__device__ int   g_lab[NROWS];
__device__ int   g_hist[1024];
__device__ int   g_is64;

// ---------------- fast exp on the FMA pipe (|x| <= ~3, rel err ~2e-6) ----------------
__device__ __forceinline__ float fexp(float s) {
    float t = s * 1.4426950408889634f;
    float z = t + 12582912.0f;
    int   n = __float_as_int(z) - 0x4B400000;
    float nf = z - 12582912.0f;
    float f = t - nf;
    float p = 1.3333558146e-3f;
    p = fmaf(p, f, 9.6181291076e-3f);
    p = fmaf(p, f, 5.5504108665e-2f);
    p = fmaf(p, f, 2.4022650696e-1f);
    p = fmaf(p, f, 6.9314718056e-1f);
    p = fmaf(p, f, 1.0f);
    return __int_as_float(__float_as_int(p) + (n << 23));
}

// ---------------- async copy helpers ----------------
#define CP_ASYNC16(dst, src) \
    asm volatile("cp.async.cg.shared.global [%0], [%1], 16;" :: "r"(dst), "l"(src))
#define CP_COMMIT() asm volatile("cp.async.commit_group;" ::: "memory")
#define CP_WAIT(n)  asm volatile("cp.async.wait_group %0;" :: "n"(n) : "memory")

__device__ __forceinline__ uint32_t smem_u32(const void* p) {
    uint32_t a;
    asm("{ .reg .u64 t; cvta.to.shared.u64 t, %1; cvt.u32.u64 %0, t; }" : "=r"(a) : "l"(p));
    return a;
}

__device__ __forceinline__ void ldmatrix_x4(uint32_t& r0, uint32_t& r1, uint32_t& r2,
                                            uint32_t& r3, uint32_t addr) {
    asm volatile("ldmatrix.sync.aligned.m8n8.x4.shared.b16 {%0,%1,%2,%3}, [%4];"
                 : "=r"(r0), "=r"(r1), "=r"(r2), "=r"(r3) : "r"(addr));
}

// e4m3 x e4m3 -> f16 accumulate, m16n8k32 (acc: 2 regs of half2)
__device__ __forceinline__ void mma_fp8_f16(uint32_t* d, const uint32_t* a,
                                            const uint32_t* b) {
    asm volatile(
        "mma.sync.aligned.m16n8k32.row.col.f16.e4m3.e4m3.f16 "
        "{%0,%1}, {%2,%3,%4,%5}, {%6,%7}, {%0,%1};"
        : "+r"(d[0]), "+r"(d[1])
        : "r"(a[0]), "r"(a[1]), "r"(a[2]), "r"(a[3]), "r"(b[0]), "r"(b[1]));
}

// pack two floats into two e4m3 bytes (hi, lo)
__device__ __forceinline__ uint16_t pack_e4m3x2(float hi, float lo) {
    uint16_t r;
    asm("cvt.rn.satfinite.e4m3x2.f32 %0, %1, %2;" : "=h"(r) : "f"(hi), "f"(lo));
    return r;
}

// ---------------- launch 0: label dtype detect + zero hist ----------------
__global__ void k_detect(const int* __restrict__ w) {
    for (int i = threadIdx.x; i < 1024; i += blockDim.x) g_hist[i] = 0;
    int ok = 1;
    for (int p = threadIdx.x; p < 4096; p += blockDim.x) {
        int lo = w[2 * p], hi = w[2 * p + 1];
        if (hi != (lo >> 31)) ok = 0;
    }
    ok = __syncthreads_and(ok);
    if (threadIdx.x == 0) g_is64 = ok;
}

// ---------------- launch 1: decode labels + histogram + zero accumulators ----------------
__global__ void k_init(const void* __restrict__ labels) {
    int i = blockIdx.x * 256 + threadIdx.x;
    if (i >= NROWS) return;
    int lab = g_is64 ? (int)((const long long*)labels)[i] : ((const int*)labels)[i];
    g_lab[i] = lab;
    if (lab >= 0) atomicAdd(&g_hist[lab & 1023], 1);
    g_rowZ[i] = 0.f; g_rowS[i] = 0.f;
    g_colZ[i] = 0.f; g_colS[i] = 0.f;
}

// ---------------- launch 2: normalize + scale + cast to e4m3 ----------------
__global__ void k_norm(const float* __restrict__ img, const float* __restrict__ txt) {
    int b = blockIdx.x;
    const float* src; uint8_t* dst; int row;
    if (b < NROWS) { src = img; dst = g_A8; row = b; }
    else           { src = txt; dst = g_B8; row = b - NROWS; }
    float4 v = ((const float4*)(src + (size_t)row * DIM))[threadIdx.x];
    float ss = v.x * v.x + v.y * v.y + v.z * v.z + v.w * v.w;
#pragma unroll
    for (int m = 16; m; m >>= 1) ss += __shfl_xor_sync(0xffffffffu, ss, m);
    __shared__ float ws[4];
    if ((threadIdx.x & 31) == 0) ws[threadIdx.x >> 5] = ss;
    __syncthreads();
    float inv = QSCALE * rsqrtf(fmaxf(ws[0] + ws[1] + ws[2] + ws[3], 1e-24f));
    uint16_t lo = pack_e4m3x2(v.y * inv, v.x * inv);
    uint16_t hi = pack_e4m3x2(v.w * inv, v.z * inv);
    uint32_t o = (uint32_t)lo | ((uint32_t)hi << 16);
    *(uint32_t*)(dst + (size_t)row * DIM + threadIdx.x * 4) = o;
}

// ---------------- launch 3: fused fp8 GEMM (f16 acc) + softmax-stat epilogue ----------------
// CTA tile 128(m) x 256(n), BK=64 bytes, 3-stage cp.async pipeline, 8 warps in
// 2(m) x 4(n) grid -> warp tile 64x64, fp16 accumulators (64 regs) so two CTAs
// fit per SM (launch_bounds 256,2; smem 72KB x 2 = 144KB).
#define STAGE_BYTES 24576

__global__ __launch_bounds__(256, 2) void k_gemm() {
    extern __shared__ char smem[];
    const uint32_t sbase = smem_u32(smem);
    const int tid = threadIdx.x;
    const int lane = tid & 31, wid = tid >> 5;
    const int wm = wid & 1, wn = wid >> 1;            // 2 x 4 warp grid
    const int i0 = blockIdx.y * 128, j0 = blockIdx.x * 256;

    const int ldr = tid >> 2;        // 0..63
    const int ldc = tid & 3;         // 16-byte chunk within the 64B stage row

    const int g = lane >> 3;         // lane group 0..3
    const int lr = lane & 7;
    uint32_t aOff[4][2], bOff[4][2];
#pragma unroll
    for (int mt = 0; mt < 4; mt++)
#pragma unroll
        for (int ks = 0; ks < 2; ks++)
            aOff[mt][ks] = (uint32_t)(((wm * 8 + mt * 2 + (g & 1)) * 4 +
                                       (ks * 2 + (g >> 1))) * 128 + lr * 16);
#pragma unroll
    for (int np = 0; np < 4; np++)
#pragma unroll
        for (int ks = 0; ks < 2; ks++)
            bOff[np][ks] = (uint32_t)(8192 + ((wn * 8 + np * 2 + (g >> 1)) * 4 +
                                              (ks * 2 + (g & 1))) * 128 + lr * 16);

    uint32_t acc[4][8][2];   // f16 accumulators (half2 pairs)
#pragma unroll
    for (int mt = 0; mt < 4; mt++)
#pragma unroll
        for (int nt = 0; nt < 8; nt++) { acc[mt][nt][0] = 0u; acc[mt][nt][1] = 0u; }

    auto load_stage = [&](int s, int kk) {
        uint32_t sA = sbase + s * STAGE_BYTES;
        uint32_t sB = sA + 8192;
#pragma unroll
        for (int h = 0; h < 2; h++) {
            int r = ldr + h * 64;
            uint32_t doff = (uint32_t)(((r >> 3) * 4 + ldc) * 128 + (r & 7) * 16);
            CP_ASYNC16(sA + doff, g_A8 + (size_t)(i0 + r) * DIM + kk + ldc * 16);
        }
#pragma unroll
        for (int h = 0; h < 4; h++) {
            int r = ldr + h * 64;
            uint32_t doff = (uint32_t)(((r >> 3) * 4 + ldc) * 128 + (r & 7) * 16);
            CP_ASYNC16(sB + doff, g_B8 + (size_t)(j0 + r) * DIM + kk + ldc * 16);
        }
    };

    load_stage(0, 0);
    CP_COMMIT();
    load_stage(1, 64);
    CP_COMMIT();

    int slot = 0, nslot = 2;
    for (int it = 0; it < 8; it++) {
        if (it <= 5) CP_WAIT(1); else CP_WAIT(0);
        __syncthreads();
        if (it + 2 <= 7) {
            load_stage(nslot, (it + 2) * 64);
            CP_COMMIT();
        }
        uint32_t stg = sbase + slot * STAGE_BYTES;
#pragma unroll
        for (int ks = 0; ks < 2; ks++) {
            uint32_t A[4][4];
#pragma unroll
            for (int mt = 0; mt < 4; mt++)
                ldmatrix_x4(A[mt][0], A[mt][1], A[mt][2], A[mt][3], stg + aOff[mt][ks]);
            uint32_t B[8][2];
#pragma unroll
            for (int np = 0; np < 4; np++) {
                uint32_t b0, b1, b2, b3;
                ldmatrix_x4(b0, b1, b2, b3, stg + bOff[np][ks]);
                B[np * 2][0] = b0;     B[np * 2][1] = b1;
                B[np * 2 + 1][0] = b2; B[np * 2 + 1][1] = b3;
            }
#pragma unroll
            for (int mt = 0; mt < 4; mt++)
#pragma unroll
                for (int nt = 0; nt < 8; nt++)
                    mma_fp8_f16(acc[mt][nt], A[mt], B[nt]);
        }
        slot = (slot == 2) ? 0 : slot + 1;
        nslot = (nslot == 2) ? 0 : nslot + 1;
    }

    // ---- epilogue: logits -> exp + target-weighted stats (registers only) ----
    // acc[mt][nt][hb] is half2 {col c, col c+1} for row (lane>>2)+mt*16+hb*8,
    // cols c = 2*(lane&3)+nt*8.  Values carry x256 (QSCALE^2) scale.
    const int r_base = i0 + wm * 64 + (lane >> 2);
    const int c_base = j0 + wn * 64 + 2 * (lane & 3);
    const float lsc = LOGIT_SCALE * INV_QS2;

    int labR[8];
#pragma unroll
    for (int q = 0; q < 8; q++) labR[q] = g_lab[r_base + (q >> 1) * 16 + (q & 1) * 8];
    int labC[16];
#pragma unroll
    for (int nt = 0; nt < 8; nt++) {
        labC[nt * 2]     = g_lab[c_base + nt * 8];
        labC[nt * 2 + 1] = g_lab[c_base + nt * 8 + 1];
    }

    float rZ[8], rS[8], cZ[16], cS[16];
#pragma unroll
    for (int q = 0; q < 8; q++) { rZ[q] = 0.f; rS[q] = 0.f; }
#pragma unroll
    for (int q = 0; q < 16; q++) { cZ[q] = 0.f; cS[q] = 0.f; }

#pragma unroll
    for (int mt = 0; mt < 4; mt++)
#pragma unroll
        for (int nt = 0; nt < 8; nt++)
#pragma unroll
            for (int hb = 0; hb < 2; hb++) {
                float2 pv = __half22float2(*(__half2*)&acc[mt][nt][hb]);
                int gi = r_base + mt * 16 + hb * 8;
                int li = labR[mt * 2 + hb];
#pragma unroll
                for (int d = 0; d < 2; d++) {
                    float sv = lsc * (d ? pv.y : pv.x);
                    float ex = fexp(sv);
                    int gj = c_base + nt * 8 + d;
                    bool tg = (gi == gj) || (li >= 0 && li == labC[nt * 2 + d]);
                    float ms = tg ? sv : 0.f;
                    rZ[mt * 2 + hb] += ex; rS[mt * 2 + hb] += ms;
                    cZ[nt * 2 + d] += ex;  cS[nt * 2 + d] += ms;
                }
            }

    // rows: reduce across the 4 lanes of each quad
#pragma unroll
    for (int m = 1; m <= 2; m <<= 1)
#pragma unroll
        for (int q = 0; q < 8; q++) {
            rZ[q] += __shfl_xor_sync(0xffffffffu, rZ[q], m);
            rS[q] += __shfl_xor_sync(0xffffffffu, rS[q], m);
        }
    if ((lane & 3) == 0) {
#pragma unroll
        for (int q = 0; q < 8; q++) {
            int gi = r_base + (q >> 1) * 16 + (q & 1) * 8;
            atomicAdd(&g_rowZ[gi], rZ[q]);
            atomicAdd(&g_rowS[gi], rS[q]);
        }
    }

    // cols: reduce across lane>>2
#pragma unroll
    for (int m = 4; m <= 16; m <<= 1)
#pragma unroll
        for (int q = 0; q < 16; q++) {
            cZ[q] += __shfl_xor_sync(0xffffffffu, cZ[q], m);
            cS[q] += __shfl_xor_sync(0xffffffffu, cS[q], m);
        }
    if (lane < 4) {
#pragma unroll
        for (int q = 0; q < 16; q++) {
            int gj = j0 + wn * 64 + (q >> 1) * 8 + 2 * lane + (q & 1);
            atomicAdd(&g_colZ[gj], cZ[q]);
            atomicAdd(&g_colS[gj], cS[q]);
        }
    }
}

// ---------------- launch 4: final reduction ----------------
__global__ void k_final(float* __restrict__ out) {
    int tid = threadIdx.x;
    float sum = 0.f;
    for (int i = tid; i < NROWS; i += 1024) {
        int l = g_lab[i];
        float inv = (l < 0) ? 1.f : 1.f / (float)g_hist[l & 1023];
        sum += logf(g_rowZ[i]) + logf(g_colZ[i]) - (g_rowS[i] + g_colS[i]) * inv;
    }
#pragma unroll
    for (int m = 16; m; m >>= 1) sum += __shfl_xor_sync(0xffffffffu, sum, m);
    __shared__ float ws[32];
    if ((tid & 31) == 0) ws[tid >> 5] = sum;
    __syncthreads();
    if (tid < 32) {
        float v = ws[tid];
#pragma unroll
        for (int m = 16; m; m >>= 1) v += __shfl_xor_sync(0xffffffffu, v, m);
        if (tid == 0) out[0] = v / (2.0f * NROWS);
    }
}

// ---------------- launch ----------------
extern "C" void kernel_launch(void* const* d_in, const int* in_sizes, int n_in,
                              void* d_out, int out_size) {
    const float* txt = (const float*)d_in[0];
    const float* img = (const float*)d_in[1];
    const void*  lab = d_in[2];

    cudaFuncSetAttribute(k_gemm, cudaFuncAttributeMaxDynamicSharedMemorySize,
                         3 * STAGE_BYTES);

    k_detect<<<1, 256>>>((const int*)lab);            // launch 0
    k_init<<<32, 256>>>(lab);                         // launch 1 (labels+hist+zero)
    k_norm<<<2 * NROWS, 128>>>(img, txt);             // launch 2
    dim3 grid(32, 64);
    k_gemm<<<grid, 256, 3 * STAGE_BYTES>>>();         // launch 3  <- ncu -s captures here
    k_final<<<1, 1024>>>((float*)d_out);              // launch 4
}